// round 9
// baseline (speedup 1.0000x reference)
#include <cuda_runtime.h>

// MixEHR_Seed: B=64, V=10000, K=64
// out: temp_exp_m_batch [64,64], temp_exp_n [V,K], temp_exp_s [V,K], gamma_sr_sum [K], exp_q_z [1]

#define KD    64
#define BD    64
#define VD    10000
#define TQ    4                 // v per tile
#define NTILE (VD / TQ)         // 2500
#define NBLK  444               // 3 CTAs x 148 SMs
#define NSLICE 32
#define VCH   64                // phase1 v-chunk
#define ETA_F  0.1f
#define BETA_F 0.05f
#define MU_F   0.05f
#define MINI_F 1e-6f

#define OFF_N   4096
#define OFF_S   644096
#define OFF_GSR 1284096
#define OFF_QZ  1284160

__device__ float g_colS[KD];
__device__ float g_colES[KD];
__device__ float g_colEN[KD];
__device__ float g_scratch32[NSLICE * BD * KD];   // 512 KB
__device__ float g_rp[BD * VD];                   // r_sum GEMM result, 2.56 MB
__device__ float g_crr[VD * KD];                  // (1-sd)*phi_n
__device__ float g_lcrr[VD * KD];                 // log(crr)
__device__ int   g_rowseed[VD];

__device__ __forceinline__ float warp_sum(float x) {
    #pragma unroll
    for (int o = 16; o; o >>= 1)
        x += __shfl_xor_sync(0xffffffffu, x, o);
    return x;
}

__global__ void zero_kernel(float* out) {
    int i = blockIdx.x * blockDim.x + threadIdx.x;     // 128*256 = 32768
    if (i < BD * KD) out[i] = 0.0f;
    if (i < KD) {
        out[OFF_GSR + i] = 0.0f;
        g_colS[i] = 0.0f; g_colES[i] = 0.0f; g_colEN[i] = 0.0f;
    }
    if (i == 0) out[OFF_QZ] = 0.0f;
    reinterpret_cast<float4*>(g_scratch32)[i] = make_float4(0.f, 0.f, 0.f, 0.f);
}

__global__ void colsum_kernel(const float* __restrict__ seeds,
                              const float* __restrict__ exp_s,
                              const float* __restrict__ exp_n) {
    int tid = blockIdx.x * blockDim.x + threadIdx.x;
    int stride = gridDim.x * blockDim.x;
    float a = 0.0f, b = 0.0f, c = 0.0f;
    for (int i = tid; i < VD * KD; i += stride) {
        a += seeds[i]; b += exp_s[i]; c += exp_n[i];
    }
    int k = tid & (KD - 1);
    atomicAdd(&g_colS[k], a);
    atomicAdd(&g_colES[k], b);
    atomicAdd(&g_colEN[k], c);
}

// Phase 1: per 64-v chunk, compute crr/lcrr/rowseed and the GEMM
// rp[b][v] = sum_k theta[b][k] * crr[v][k].
__global__ __launch_bounds__(256) void phase1_kernel(
    const float* __restrict__ seeds,
    const float* __restrict__ exp_m,
    const float* __restrict__ exp_n)
{
    __shared__ float sTh[BD * KD];        // theta[b][k]
    __shared__ float sC[KD][VCH + 1];     // crr[k][vloc], padded
    __shared__ float sInvN[KD];

    const int tid = threadIdx.x;
    const int v0 = blockIdx.x * VCH;

    for (int i = tid; i < BD * KD; i += 256)
        sTh[i] = exp_m[i] + ETA_F;
    if (tid < KD)
        sInvN[tid] = __fdividef(1.0f, BETA_F * (float)VD + g_colEN[tid]);
    __syncthreads();

    for (int i = tid; i < VCH * KD; i += 256) {
        const int vl = i >> 6, k = i & 63;
        const int gv = v0 + vl;
        float crr = 0.0f;
        if (gv < VD) {
            const float sd = seeds[gv * KD + k];
            const float en = exp_n[gv * KD + k];
            crr = (1.0f - sd) * (BETA_F + en) * sInvN[k];
            g_crr[gv * KD + k] = crr;
            g_lcrr[gv * KD + k] = __logf(crr + 1e-30f);
        }
        sC[k][vl] = crr;
    }
    // per-row seed flags
    if (tid < VCH) {
        const int gv = v0 + tid;
        if (gv < VD) {
            const float4* sr = reinterpret_cast<const float4*>(seeds + gv * KD);
            int f = 0;
            #pragma unroll
            for (int q = 0; q < 16; q++) {
                float4 s4 = sr[q];
                f |= (s4.x > 0.0f) | (s4.y > 0.0f) | (s4.z > 0.0f) | (s4.w > 0.0f);
            }
            g_rowseed[gv] = f;
        }
    }
    __syncthreads();

    // 4b x 4v register tile per thread
    const int tx = tid & 15, ty = tid >> 4;
    float rp[4][4];
    #pragma unroll
    for (int i = 0; i < 4; i++)
        #pragma unroll
        for (int j = 0; j < 4; j++) rp[i][j] = 0.0f;

    #pragma unroll 4
    for (int k = 0; k < KD; k++) {
        float a0 = sTh[(ty * 4 + 0) * KD + k];
        float a1 = sTh[(ty * 4 + 1) * KD + k];
        float a2 = sTh[(ty * 4 + 2) * KD + k];
        float a3 = sTh[(ty * 4 + 3) * KD + k];
        float c0 = sC[k][tx * 4 + 0];
        float c1 = sC[k][tx * 4 + 1];
        float c2 = sC[k][tx * 4 + 2];
        float c3 = sC[k][tx * 4 + 3];
        rp[0][0] = fmaf(a0, c0, rp[0][0]); rp[0][1] = fmaf(a0, c1, rp[0][1]);
        rp[0][2] = fmaf(a0, c2, rp[0][2]); rp[0][3] = fmaf(a0, c3, rp[0][3]);
        rp[1][0] = fmaf(a1, c0, rp[1][0]); rp[1][1] = fmaf(a1, c1, rp[1][1]);
        rp[1][2] = fmaf(a1, c2, rp[1][2]); rp[1][3] = fmaf(a1, c3, rp[1][3]);
        rp[2][0] = fmaf(a2, c0, rp[2][0]); rp[2][1] = fmaf(a2, c1, rp[2][1]);
        rp[2][2] = fmaf(a2, c2, rp[2][2]); rp[2][3] = fmaf(a2, c3, rp[2][3]);
        rp[3][0] = fmaf(a3, c0, rp[3][0]); rp[3][1] = fmaf(a3, c1, rp[3][1]);
        rp[3][2] = fmaf(a3, c2, rp[3][2]); rp[3][3] = fmaf(a3, c3, rp[3][3]);
    }
    #pragma unroll
    for (int i = 0; i < 4; i++) {
        const int b = ty * 4 + i;
        #pragma unroll
        for (int j = 0; j < 4; j++) {
            const int gv = v0 + tx * 4 + j;
            if (gv < VD) g_rp[b * VD + gv] = rp[i][j];
        }
    }
}

__global__ __launch_bounds__(256, 3) void main_kernel(
    const float* __restrict__ BOW,
    const float* __restrict__ seeds,
    const float* __restrict__ exp_m,
    const float* __restrict__ exp_s,
    const float* __restrict__ exp_n,
    const float* __restrict__ pi,
    float* __restrict__ out)
{
    __shared__ float2 sh_thlt[BD * KD];     // {theta, log(theta)}  32 KB
    __shared__ float  sh_pN[8][TQ * KD];    //  8 KB
    __shared__ float  sh_pS[8][TQ * KD];    //  8 KB
    __shared__ float  sh_gsr[KD];
    __shared__ float  sh_qz;

    for (int i = threadIdx.x; i < BD * KD; i += blockDim.x) {
        float th = exp_m[i] + ETA_F;
        sh_thlt[i] = make_float2(th, __logf(th));
    }
    if (threadIdx.x < KD) sh_gsr[threadIdx.x] = 0.0f;
    if (threadIdx.x == 0) sh_qz = 0.0f;
    __syncthreads();

    const int lane = threadIdx.x & 31;
    const int warp = threadIdx.x >> 5;
    const int k0 = lane, k1 = lane + 32;
    const int b0 = warp * 8;

    const float invS0 = 1.0f / (MU_F * g_colS[k0] + g_colES[k0]);
    const float invS1 = 1.0f / (MU_F * g_colS[k1] + g_colES[k1]);
    const float invN0 = 1.0f / (BETA_F * (float)VD + g_colEN[k0]);
    const float invN1 = 1.0f / (BETA_F * (float)VD + g_colEN[k1]);
    const float pi0 = pi[k0], pi1 = pi[k1];
    const float q0 = 1.0f - pi0, q1 = 1.0f - pi1;

    float accM0[8], accM1[8];
    #pragma unroll
    for (int j = 0; j < 8; j++) { accM0[j] = 0.0f; accM1[j] = 0.0f; }
    float accGsr0 = 0.0f, accGsr1 = 0.0f, accQz = 0.0f;

    for (int tile = blockIdx.x; tile < NTILE; tile += gridDim.x) {
        const int v0 = tile * TQ;

        const int4 flg = reinterpret_cast<const int4*>(g_rowseed)[tile];
        const int rs[TQ] = {flg.x, flg.y, flg.z, flg.w};
        const bool tileseed = (flg.x | flg.y | flg.z | flg.w) != 0;

        float crr0[TQ], crr1[TQ], lc0[TQ], lc1[TQ];
        #pragma unroll
        for (int t = 0; t < TQ; t++) {
            const int base = (v0 + t) * KD;
            crr0[t] = g_crr[base + k0];
            crr1[t] = g_crr[base + k1];
            lc0[t]  = g_lcrr[base + k0];
            lc1[t]  = g_lcrr[base + k1];
        }

        float aN0[TQ], aN1[TQ], aS0[TQ], aS1[TQ];
        #pragma unroll
        for (int t = 0; t < TQ; t++) { aN0[t]=0.f; aN1[t]=0.f; aS0[t]=0.f; aS1[t]=0.f; }

        if (!tileseed) {
            // ---------------- FAST PATH (no shuffles) ----------------
            #pragma unroll
            for (int j = 0; j < 8; j++) {
                const int b = b0 + j;
                const float4 c4 = *reinterpret_cast<const float4*>(BOW + b * VD + v0);
                const float4 r4 = *reinterpret_cast<const float4*>(g_rp + b * VD + v0);
                const float cntv[TQ] = {c4.x, c4.y, c4.z, c4.w};
                const float rpv[TQ]  = {r4.x, r4.y, r4.z, r4.w};
                const float2 tl0 = sh_thlt[b * KD + k0];
                const float2 tl1 = sh_thlt[b * KD + k1];

                #pragma unroll
                for (int t = 0; t < TQ; t++) {
                    const float rpm = rpv[t] + MINI_F;
                    const float inv = __fdividef(1.0f, rpm);
                    const float lrp = __logf(rpm);
                    const float g0 = tl0.x * crr0[t] * inv;
                    const float g1 = tl1.x * crr1[t] * inv;
                    const float cnt = cntv[t];
                    const float p0 = g0 * cnt, p1 = g1 * cnt;
                    aN0[t] += p0; aN1[t] += p1;
                    accM0[j] += p0; accM1[j] += p1;
                    const float m = (cnt > 0.0f) ? 1.0f : 0.0f;
                    const float e = g0 * ((tl0.y + lc0[t]) - lrp)
                                  + g1 * ((tl1.y + lc1[t]) - lrp);
                    accQz = fmaf(m, e, accQz);
                }
            }
        } else {
            // ---------------- SEED-TILE PATH ----------------
            #pragma unroll
            for (int j = 0; j < 8; j++) {
                const int b = b0 + j;
                const float4 c4 = *reinterpret_cast<const float4*>(BOW + b * VD + v0);
                const float4 r4 = *reinterpret_cast<const float4*>(g_rp + b * VD + v0);
                const float cntv[TQ] = {c4.x, c4.y, c4.z, c4.w};
                const float rpv[TQ]  = {r4.x, r4.y, r4.z, r4.w};
                const float2 tl0 = sh_thlt[b * KD + k0];
                const float2 tl1 = sh_thlt[b * KD + k1];

                #pragma unroll
                for (int t = 0; t < TQ; t++) {
                    const float cnt = cntv[t];
                    const float m = (cnt > 0.0f) ? 1.0f : 0.0f;
                    const float invr = __fdividef(1.0f, rpv[t] + MINI_F);
                    if (rs[t]) {
                        const int base = (v0 + t) * KD;
                        const float sd0 = seeds[base + k0], sd1 = seeds[base + k1];
                        const float ps0 = (MU_F  + exp_s[base + k0]) * invS0;
                        const float ps1 = (MU_F  + exp_s[base + k1]) * invS1;
                        const float pn0 = (BETA_F + exp_n[base + k0]) * invN0;
                        const float pn1 = (BETA_F + exp_n[base + k1]) * invN1;
                        float gss0 = tl0.x * sd0 * ps0 * pi0;
                        float gss1 = tl1.x * sd1 * ps1 * pi1;
                        float gsr0 = tl0.x * sd0 * pn0 * q0;
                        float gsr1 = tl1.x * sd1 * pn1 * q1;
                        float grr0 = tl0.x * crr0[t];
                        float grr1 = tl1.x * crr1[t];
                        const float sp = warp_sum(gss0 + gsr0 + gss1 + gsr1);
                        const float invs = __fdividef(1.0f, sp + MINI_F);
                        gss0 *= invs; gss1 *= invs;
                        gsr0 *= invs; gsr1 *= invs;
                        grr0 *= invr; grr1 *= invr;
                        const float gam0 = pi0 * gss0 + q0 * (gsr0 + grr0);
                        const float gam1 = pi1 * gss1 + q1 * (gsr1 + grr1);
                        accM0[j] += gam0 * cnt; accM1[j] += gam1 * cnt;
                        aN0[t] += (gsr0 + grr0) * cnt; aN1[t] += (gsr1 + grr1) * cnt;
                        aS0[t] += gss0 * cnt;          aS1[t] += gss1 * cnt;
                        accGsr0 += m * gsr0;           accGsr1 += m * gsr1;
                        accQz += m * (gam0 * __logf(gam0 + MINI_F)
                                    + gam1 * __logf(gam1 + MINI_F));
                    } else {
                        const float lrp = __logf(rpv[t] + MINI_F);
                        const float g0 = tl0.x * crr0[t] * invr;
                        const float g1 = tl1.x * crr1[t] * invr;
                        const float p0 = g0 * cnt, p1 = g1 * cnt;
                        aN0[t] += p0; aN1[t] += p1;
                        accM0[j] += p0; accM1[j] += p1;
                        const float e = g0 * ((tl0.y + lc0[t]) - lrp)
                                      + g1 * ((tl1.y + lc1[t]) - lrp);
                        accQz = fmaf(m, e, accQz);
                    }
                }
            }
        }

        #pragma unroll
        for (int t = 0; t < TQ; t++) {
            sh_pN[warp][t * KD + k0] = aN0[t];
            sh_pN[warp][t * KD + k1] = aN1[t];
            sh_pS[warp][t * KD + k0] = aS0[t];
            sh_pS[warp][t * KD + k1] = aS1[t];
        }
        __syncthreads();
        {
            const int tid = threadIdx.x;   // tid = t*64 + k
            float sN = 0.0f;
            #pragma unroll
            for (int w = 0; w < 8; w++) sN += sh_pN[w][tid];
            out[OFF_N + v0 * KD + tid] = sN;
            float sS = 0.0f;
            if (tileseed) {
                #pragma unroll
                for (int w = 0; w < 8; w++) sS += sh_pS[w][tid];
            }
            out[OFF_S + v0 * KD + tid] = sS;
        }
        __syncthreads();
    }

    // epilogue
    {
        float* dst = g_scratch32 + (blockIdx.x & (NSLICE - 1)) * (BD * KD);
        #pragma unroll
        for (int j = 0; j < 8; j++) {
            atomicAdd(&dst[(b0 + j) * KD + k0], accM0[j]);
            atomicAdd(&dst[(b0 + j) * KD + k1], accM1[j]);
        }
    }
    atomicAdd(&sh_gsr[k0], accGsr0);
    atomicAdd(&sh_gsr[k1], accGsr1);
    const float qzw = warp_sum(accQz);
    if (lane == 0) atomicAdd(&sh_qz, qzw);
    __syncthreads();
    if (threadIdx.x < KD) atomicAdd(&out[OFF_GSR + threadIdx.x], sh_gsr[threadIdx.x]);
    if (threadIdx.x == 0) atomicAdd(&out[OFF_QZ], sh_qz);
}

// Sum scratch32[32][4096] -> out. grid (16,8): 4 slices per y-chunk.
__global__ void reduce_m_kernel(float* __restrict__ out) {
    const int i = blockIdx.x * blockDim.x + threadIdx.x;   // 0..4095
    const int j0 = blockIdx.y * 4;
    float s = 0.0f;
    #pragma unroll
    for (int j = 0; j < 4; j++)
        s += g_scratch32[(j0 + j) * (BD * KD) + i];
    atomicAdd(&out[i], s);
}

extern "C" void kernel_launch(void* const* d_in, const int* in_sizes, int n_in,
                              void* d_out, int out_size) {
    const float* BOW   = (const float*)d_in[0];
    const float* seeds = (const float*)d_in[1];
    const float* exp_m = (const float*)d_in[2];
    const float* exp_s = (const float*)d_in[3];
    const float* exp_n = (const float*)d_in[4];
    const float* pi    = (const float*)d_in[5];
    float* out = (float*)d_out;

    zero_kernel<<<128, 256>>>(out);
    colsum_kernel<<<592, 256>>>(seeds, exp_s, exp_n);
    phase1_kernel<<<(VD + VCH - 1) / VCH, 256>>>(seeds, exp_m, exp_n);
    main_kernel<<<NBLK, 256>>>(BOW, seeds, exp_m, exp_s, exp_n, pi, out);
    reduce_m_kernel<<<dim3(16, 8), 256>>>(out);
}

// round 10
// speedup vs baseline: 1.0931x; 1.0931x over previous
#include <cuda_runtime.h>

// MixEHR_Seed: B=64, V=10000, K=64
// out: temp_exp_m_batch [64,64], temp_exp_n [V,K], temp_exp_s [V,K], gamma_sr_sum [K], exp_q_z [1]

#define KD    64
#define BD    64
#define VD    10000
#define TQ    4                 // v per tile
#define NTILE (VD / TQ)         // 2500
#define NBLK  444               // 3 CTAs x 148 SMs
#define NSLICE 32
#define ETA_F  0.1f
#define BETA_F 0.05f
#define MU_F   0.05f
#define MINI_F 1e-6f

#define OFF_N   4096
#define OFF_S   644096
#define OFF_GSR 1284096
#define OFF_QZ  1284160

__device__ float g_colS[KD];
__device__ float g_colES[KD];
__device__ float g_colEN[KD];
__device__ float g_scratch32[NSLICE * BD * KD];   // 512 KB

__device__ __forceinline__ float warp_sum(float x) {
    #pragma unroll
    for (int o = 16; o; o >>= 1)
        x += __shfl_xor_sync(0xffffffffu, x, o);
    return x;
}

__device__ __forceinline__ void cp16(void* dst_smem, const void* src_gmem) {
    unsigned int d = (unsigned int)__cvta_generic_to_shared(dst_smem);
    asm volatile("cp.async.ca.shared.global [%0], [%1], 16;" :: "r"(d), "l"(src_gmem));
}

__global__ void zero_kernel(float* out) {
    int i = blockIdx.x * blockDim.x + threadIdx.x;     // 128*256 = 32768
    if (i < BD * KD) out[i] = 0.0f;
    if (i < KD) {
        out[OFF_GSR + i] = 0.0f;
        g_colS[i] = 0.0f; g_colES[i] = 0.0f; g_colEN[i] = 0.0f;
    }
    if (i == 0) out[OFF_QZ] = 0.0f;
    reinterpret_cast<float4*>(g_scratch32)[i] = make_float4(0.f, 0.f, 0.f, 0.f);
}

__global__ void colsum_kernel(const float* __restrict__ seeds,
                              const float* __restrict__ exp_s,
                              const float* __restrict__ exp_n) {
    int tid = blockIdx.x * blockDim.x + threadIdx.x;
    int stride = gridDim.x * blockDim.x;
    float a = 0.0f, b = 0.0f, c = 0.0f;
    for (int i = tid; i < VD * KD; i += stride) {
        a += seeds[i]; b += exp_s[i]; c += exp_n[i];
    }
    int k = tid & (KD - 1);
    atomicAdd(&g_colS[k], a);
    atomicAdd(&g_colES[k], b);
    atomicAdd(&g_colEN[k], c);
}

__global__ __launch_bounds__(256, 3) void main_kernel(
    const float* __restrict__ BOW,
    const float* __restrict__ seeds,
    const float* __restrict__ exp_m,
    const float* __restrict__ exp_s,
    const float* __restrict__ exp_n,
    const float* __restrict__ pi,
    float* __restrict__ out)
{
    __shared__ float2 sh_thlt[BD * KD];        // {theta, log theta}  32 KB
    __shared__ float  sh_pN[8][TQ * KD];       //  8 KB
    __shared__ float  sh_pS[8][TQ * KD];       //  8 KB
    __shared__ float  sh_seed[2][TQ * KD];     //  2 KB  (prefetch)
    __shared__ float  sh_en[2][TQ * KD];       //  2 KB  (prefetch)
    __shared__ float  sh_bow[2][BD * TQ];      //  2 KB  (prefetch)
    __shared__ float  sh_gsr[KD];
    __shared__ float  sh_qz;

    const int tid = threadIdx.x;

    for (int i = tid; i < BD * KD; i += blockDim.x) {
        float th = exp_m[i] + ETA_F;
        sh_thlt[i] = make_float2(th, __logf(th));
    }
    if (tid < KD) sh_gsr[tid] = 0.0f;
    if (tid == 0) sh_qz = 0.0f;

    const int lane = tid & 31;
    const int warp = tid >> 5;
    const int k0 = lane, k1 = lane + 32;
    const int b0 = warp * 8;

    const float invS0 = 1.0f / (MU_F * g_colS[k0] + g_colES[k0]);
    const float invS1 = 1.0f / (MU_F * g_colS[k1] + g_colES[k1]);
    const float invN0 = 1.0f / (BETA_F * (float)VD + g_colEN[k0]);
    const float invN1 = 1.0f / (BETA_F * (float)VD + g_colEN[k1]);
    const float pi0 = pi[k0], pi1 = pi[k1];
    const float q0 = 1.0f - pi0, q1 = 1.0f - pi1;

    float accM0[8], accM1[8];
    #pragma unroll
    for (int j = 0; j < 8; j++) { accM0[j] = 0.0f; accM1[j] = 0.0f; }
    float accGsr0 = 0.0f, accGsr1 = 0.0f, accQz = 0.0f;

    // ---- prefetch helper (lambda-free, inline) ----
    // tid 0..63   -> seeds rows v0..v0+3 (contiguous 1KB)
    // tid 64..127 -> exp_n rows (contiguous 1KB)
    // tid 128..191-> BOW[b][v0..v0+3] per b (64 x 16B strided)
    #define PREFETCH(T, BUF)                                                     \
        do { int _t = (T);                                                       \
            if (_t < NTILE) {                                                    \
                const int _v0 = _t * TQ;                                         \
                if (tid < 64)        cp16(&sh_seed[BUF][tid * 4],                \
                                          seeds + _v0 * KD + tid * 4);           \
                else if (tid < 128)  cp16(&sh_en[BUF][(tid - 64) * 4],           \
                                          exp_n + _v0 * KD + (tid - 64) * 4);    \
                else if (tid < 192)  cp16(&sh_bow[BUF][(tid - 128) * 4],         \
                                          BOW + (tid - 128) * VD + _v0);         \
            }                                                                    \
            asm volatile("cp.async.commit_group;");                              \
        } while (0)

    PREFETCH(blockIdx.x, 0);
    int buf = 0;

    for (int tile = blockIdx.x; tile < NTILE; tile += gridDim.x) {
        const int v0 = tile * TQ;

        PREFETCH(tile + gridDim.x, buf ^ 1);
        asm volatile("cp.async.wait_group 1;");
        __syncthreads();                         // current buffer visible block-wide

        // per-row constants from shared
        float crr0[TQ], crr1[TQ], lc0[TQ], lc1[TQ];
        bool rowseed[TQ];
        bool tileseed = false;
        #pragma unroll
        for (int t = 0; t < TQ; t++) {
            const float sd0 = sh_seed[buf][t * KD + k0];
            const float sd1 = sh_seed[buf][t * KD + k1];
            const float pn0 = (BETA_F + sh_en[buf][t * KD + k0]) * invN0;
            const float pn1 = (BETA_F + sh_en[buf][t * KD + k1]) * invN1;
            crr0[t] = (1.0f - sd0) * pn0;
            crr1[t] = (1.0f - sd1) * pn1;
            rowseed[t] = __ballot_sync(0xffffffffu, (sd0 > 0.0f) || (sd1 > 0.0f)) != 0u;
            tileseed |= rowseed[t];
            lc0[t] = __logf(crr0[t] + 1e-30f);
            lc1[t] = __logf(crr1[t] + 1e-30f);
        }

        float aN0[TQ], aN1[TQ], aS0[TQ], aS1[TQ];
        #pragma unroll
        for (int t = 0; t < TQ; t++) { aN0[t]=0.f; aN1[t]=0.f; aS0[t]=0.f; aS1[t]=0.f; }

        if (!tileseed) {
            // ---------------- FAST PATH ----------------
            #pragma unroll
            for (int j = 0; j < 8; j++) {
                const int b = b0 + j;
                const float4 c4 = *reinterpret_cast<const float4*>(&sh_bow[buf][b * 4]);
                const float cntv[TQ] = {c4.x, c4.y, c4.z, c4.w};
                const float2 tl0 = sh_thlt[b * KD + k0];
                const float2 tl1 = sh_thlt[b * KD + k1];

                float grr0v[TQ], grr1v[TQ], rpv[TQ];
                #pragma unroll
                for (int t = 0; t < TQ; t++) {
                    grr0v[t] = tl0.x * crr0[t];
                    grr1v[t] = tl1.x * crr1[t];
                    rpv[t] = grr0v[t] + grr1v[t];
                }
                #pragma unroll
                for (int o = 16; o; o >>= 1) {
                    #pragma unroll
                    for (int t = 0; t < TQ; t++)
                        rpv[t] += __shfl_xor_sync(0xffffffffu, rpv[t], o);
                }
                #pragma unroll
                for (int t = 0; t < TQ; t++) {
                    const float rpm = rpv[t] + MINI_F;
                    const float inv = __fdividef(1.0f, rpm);
                    const float lrp = __logf(rpm);
                    const float g0 = grr0v[t] * inv;
                    const float g1 = grr1v[t] * inv;
                    const float cnt = cntv[t];
                    const float p0 = g0 * cnt, p1 = g1 * cnt;
                    aN0[t] += p0; aN1[t] += p1;
                    accM0[j] += p0; accM1[j] += p1;
                    const float m = (cnt > 0.0f) ? 1.0f : 0.0f;
                    const float e = g0 * ((tl0.y + lc0[t]) - lrp)
                                  + g1 * ((tl1.y + lc1[t]) - lrp);
                    accQz = fmaf(m, e, accQz);
                }
            }
        } else {
            // ---------------- SEED-TILE PATH ----------------
            #pragma unroll
            for (int j = 0; j < 8; j++) {
                const int b = b0 + j;
                const float4 c4 = *reinterpret_cast<const float4*>(&sh_bow[buf][b * 4]);
                const float cntv[TQ] = {c4.x, c4.y, c4.z, c4.w};
                const float2 tl0 = sh_thlt[b * KD + k0];
                const float2 tl1 = sh_thlt[b * KD + k1];

                #pragma unroll
                for (int t = 0; t < TQ; t++) {
                    const float cnt = cntv[t];
                    const float m = (cnt > 0.0f) ? 1.0f : 0.0f;
                    if (rowseed[t]) {
                        const int base = (v0 + t) * KD;
                        const float sd0 = sh_seed[buf][t * KD + k0];
                        const float sd1 = sh_seed[buf][t * KD + k1];
                        const float ps0 = (MU_F  + exp_s[base + k0]) * invS0;
                        const float ps1 = (MU_F  + exp_s[base + k1]) * invS1;
                        const float pn0 = (BETA_F + sh_en[buf][t * KD + k0]) * invN0;
                        const float pn1 = (BETA_F + sh_en[buf][t * KD + k1]) * invN1;
                        float gss0 = tl0.x * sd0 * ps0 * pi0;
                        float gss1 = tl1.x * sd1 * ps1 * pi1;
                        float gsr0 = tl0.x * sd0 * pn0 * q0;
                        float gsr1 = tl1.x * sd1 * pn1 * q1;
                        float grr0 = tl0.x * crr0[t];
                        float grr1 = tl1.x * crr1[t];
                        float sp = gss0 + gsr0 + gss1 + gsr1;
                        float rp = grr0 + grr1;
                        #pragma unroll
                        for (int o = 16; o; o >>= 1) {
                            sp += __shfl_xor_sync(0xffffffffu, sp, o);
                            rp += __shfl_xor_sync(0xffffffffu, rp, o);
                        }
                        const float invs = __fdividef(1.0f, sp + MINI_F);
                        const float invr = __fdividef(1.0f, rp + MINI_F);
                        gss0 *= invs; gss1 *= invs;
                        gsr0 *= invs; gsr1 *= invs;
                        grr0 *= invr; grr1 *= invr;
                        const float gam0 = pi0 * gss0 + q0 * (gsr0 + grr0);
                        const float gam1 = pi1 * gss1 + q1 * (gsr1 + grr1);
                        accM0[j] += gam0 * cnt; accM1[j] += gam1 * cnt;
                        aN0[t] += (gsr0 + grr0) * cnt; aN1[t] += (gsr1 + grr1) * cnt;
                        aS0[t] += gss0 * cnt;          aS1[t] += gss1 * cnt;
                        accGsr0 += m * gsr0;           accGsr1 += m * gsr1;
                        accQz += m * (gam0 * __logf(gam0 + MINI_F)
                                    + gam1 * __logf(gam1 + MINI_F));
                    } else {
                        float grr0 = tl0.x * crr0[t];
                        float grr1 = tl1.x * crr1[t];
                        const float rpm = warp_sum(grr0 + grr1) + MINI_F;
                        const float inv = __fdividef(1.0f, rpm);
                        const float lrp = __logf(rpm);
                        const float g0 = grr0 * inv, g1 = grr1 * inv;
                        const float p0 = g0 * cnt, p1 = g1 * cnt;
                        aN0[t] += p0; aN1[t] += p1;
                        accM0[j] += p0; accM1[j] += p1;
                        const float e = g0 * ((tl0.y + lc0[t]) - lrp)
                                      + g1 * ((tl1.y + lc1[t]) - lrp);
                        accQz = fmaf(m, e, accQz);
                    }
                }
            }
        }

        // cross-warp reduce of aN/aS, store temp_exp_n / temp_exp_s
        #pragma unroll
        for (int t = 0; t < TQ; t++) {
            sh_pN[warp][t * KD + k0] = aN0[t];
            sh_pN[warp][t * KD + k1] = aN1[t];
            sh_pS[warp][t * KD + k0] = aS0[t];
            sh_pS[warp][t * KD + k1] = aS1[t];
        }
        __syncthreads();
        {
            float sN = 0.0f;
            #pragma unroll
            for (int w = 0; w < 8; w++) sN += sh_pN[w][tid];
            out[OFF_N + v0 * KD + tid] = sN;
            float sS = 0.0f;
            if (tileseed) {
                #pragma unroll
                for (int w = 0; w < 8; w++) sS += sh_pS[w][tid];
            }
            out[OFF_S + v0 * KD + tid] = sS;
        }
        __syncthreads();
        buf ^= 1;
    }

    // epilogue: exp_m partials -> 32-slice scratch via spread atomics
    {
        float* dst = g_scratch32 + (blockIdx.x & (NSLICE - 1)) * (BD * KD);
        #pragma unroll
        for (int j = 0; j < 8; j++) {
            atomicAdd(&dst[(b0 + j) * KD + k0], accM0[j]);
            atomicAdd(&dst[(b0 + j) * KD + k1], accM1[j]);
        }
    }
    atomicAdd(&sh_gsr[k0], accGsr0);
    atomicAdd(&sh_gsr[k1], accGsr1);
    const float qzw = warp_sum(accQz);
    if (lane == 0) atomicAdd(&sh_qz, qzw);
    __syncthreads();
    if (tid < KD) atomicAdd(&out[OFF_GSR + tid], sh_gsr[tid]);
    if (tid == 0) atomicAdd(&out[OFF_QZ], sh_qz);
}

// Sum scratch32[32][4096] -> out. grid (16,8): 4 slices per y-chunk.
__global__ void reduce_m_kernel(float* __restrict__ out) {
    const int i = blockIdx.x * blockDim.x + threadIdx.x;   // 0..4095
    const int j0 = blockIdx.y * 4;
    float s = 0.0f;
    #pragma unroll
    for (int j = 0; j < 4; j++)
        s += g_scratch32[(j0 + j) * (BD * KD) + i];
    atomicAdd(&out[i], s);
}

extern "C" void kernel_launch(void* const* d_in, const int* in_sizes, int n_in,
                              void* d_out, int out_size) {
    const float* BOW   = (const float*)d_in[0];
    const float* seeds = (const float*)d_in[1];
    const float* exp_m = (const float*)d_in[2];
    const float* exp_s = (const float*)d_in[3];
    const float* exp_n = (const float*)d_in[4];
    const float* pi    = (const float*)d_in[5];
    float* out = (float*)d_out;

    zero_kernel<<<128, 256>>>(out);
    colsum_kernel<<<592, 256>>>(seeds, exp_s, exp_n);
    main_kernel<<<NBLK, 256>>>(BOW, seeds, exp_m, exp_s, exp_n, pi, out);
    reduce_m_kernel<<<dim3(16, 8), 256>>>(out);
}